// round 1
// baseline (speedup 1.0000x reference)
#include <cuda_runtime.h>
#include <math.h>

#define VD 32
#define ID 64
#define KF 2048
#define NMAX 32768

// Scratch (device globals: allocation-free rule)
__device__ float g_y[(size_t)NMAX * 64];  // [N,64]: cols 0..31 = flat@W1+b1, cols 32..63 = flat@Ws+bs
__device__ float g_w[(size_t)NMAX * VD];  // softmax weights [N,32]

__device__ __forceinline__ float sigmoidf_(float x) { return 1.f / (1.f + __expf(-x)); }
__device__ __forceinline__ float eluf_(float x) { return x > 0.f ? x : expm1f(x); }

__device__ __forceinline__ float wsum_(float v) {
    #pragma unroll
    for (int o = 16; o > 0; o >>= 1) v += __shfl_xor_sync(0xffffffffu, v, o);
    return v;
}
__device__ __forceinline__ float wmax_(float v) {
    #pragma unroll
    for (int o = 16; o > 0; o >>= 1) v = fmaxf(v, __shfl_xor_sync(0xffffffffu, v, o));
    return v;
}

// ============================================================
// Kernel A1: Y[N,64] = flat[N,2048] @ [W1 | Ws] + [b1 | bs]
// CTA: 128 tokens x 64 cols; thread: 8 tokens x 4 cols
// ============================================================
__global__ void __launch_bounds__(256) kA1(
    const float* __restrict__ x,
    const float* __restrict__ W1, const float* __restrict__ b1,
    const float* __restrict__ Ws, const float* __restrict__ bs)
{
    __shared__ float Xs[32 * 132];  // [k][token], pitch 132
    __shared__ float Bs[32 * 64];   // [k][col]

    const int tid = threadIdx.x;
    const int cx = tid & 15, ty = tid >> 4;
    const int tok0 = blockIdx.x * 128;

    float acc[8][4];
    #pragma unroll
    for (int cc = 0; cc < 4; cc++) {
        int c = cx * 4 + cc;
        float bb = (c < 32) ? b1[c] : bs[c - 32];
        #pragma unroll
        for (int r = 0; r < 8; r++) acc[r][cc] = bb;
    }

    for (int k0 = 0; k0 < KF; k0 += 32) {
        #pragma unroll
        for (int p = 0; p < 16; p++) {
            int i = tid + p * 256;
            int kk = i & 31, t = i >> 5;
            Xs[kk * 132 + t] = x[(size_t)(tok0 + t) * KF + k0 + kk];
        }
        #pragma unroll
        for (int p = 0; p < 8; p++) {
            int i = tid + p * 256;
            int j = i & 63, kk = i >> 6;
            Bs[kk * 64 + j] = (j < 32) ? W1[(size_t)(k0 + kk) * 32 + j]
                                       : Ws[(size_t)(k0 + kk) * 32 + (j - 32)];
        }
        __syncthreads();

        #pragma unroll 4
        for (int kk = 0; kk < 32; kk++) {
            const float4 a0 = *(const float4*)&Xs[kk * 132 + ty * 8];
            const float4 a1 = *(const float4*)&Xs[kk * 132 + ty * 8 + 4];
            const float4 b  = *(const float4*)&Bs[kk * 64 + cx * 4];
            float av[8] = {a0.x, a0.y, a0.z, a0.w, a1.x, a1.y, a1.z, a1.w};
            float bv[4] = {b.x, b.y, b.z, b.w};
            #pragma unroll
            for (int r = 0; r < 8; r++)
                #pragma unroll
                for (int cc = 0; cc < 4; cc++)
                    acc[r][cc] = fmaf(av[r], bv[cc], acc[r][cc]);
        }
        __syncthreads();
    }

    #pragma unroll
    for (int r = 0; r < 8; r++) {
        float4 o = {acc[r][0], acc[r][1], acc[r][2], acc[r][3]};
        *(float4*)&g_y[(size_t)(tok0 + ty * 8 + r) * 64 + cx * 4] = o;
    }
}

// ============================================================
// Kernel A2: per-token tail of the weight GRN. One warp = one token.
// t = elu(h)@W2+b2 ; g = t@Wg+bg ; z = skip + glu(g) ; LN ; softmax -> g_w
// ============================================================
__global__ void __launch_bounds__(256) kA2(
    const float* __restrict__ W2, const float* __restrict__ b2,
    const float* __restrict__ Wg, const float* __restrict__ bg,
    const float* __restrict__ gam, const float* __restrict__ bet, int N)
{
    __shared__ float W2s[32 * 33];
    __shared__ float Wgs[32 * 64];
    const int tid = threadIdx.x;
    for (int i = tid; i < 1024; i += 256) W2s[(i >> 5) * 33 + (i & 31)] = W2[i];
    for (int i = tid; i < 2048; i += 256) Wgs[i] = Wg[i];
    __syncthreads();

    const int lane = tid & 31, warp = tid >> 5;
    const int tok = blockIdx.x * 8 + warp;
    if (tok >= N) return;

    const float* y = &g_y[(size_t)tok * 64];
    float hpre = y[lane];
    float skip = y[32 + lane];
    float h = eluf_(hpre);

    float t = b2[lane];
    #pragma unroll
    for (int i = 0; i < 32; i++)
        t = fmaf(__shfl_sync(0xffffffffu, h, i), W2s[i * 33 + lane], t);

    float ga = bg[lane], gb = bg[32 + lane];
    #pragma unroll
    for (int i = 0; i < 32; i++) {
        float tv = __shfl_sync(0xffffffffu, t, i);
        ga = fmaf(tv, Wgs[i * 64 + lane], ga);
        gb = fmaf(tv, Wgs[i * 64 + 32 + lane], gb);
    }

    float z = skip + ga * sigmoidf_(gb);
    float m = wsum_(z) * (1.f / 32.f);
    float d = z - m;
    float var = wsum_(d * d) * (1.f / 32.f);
    float zn = d * rsqrtf(var + 1e-5f) * gam[lane] + bet[lane];

    float mx = wmax_(zn);
    float e = __expf(zn - mx);
    float se = wsum_(e);
    g_w[(size_t)tok * VD + lane] = e / se;
}

// ============================================================
// Kernel B: per-variable GRNs + weighted combine.
// CTA: 128 tokens; loop v=0..31 with weights staged in smem.
// ============================================================
__device__ __forceinline__ void gemm64(const float* __restrict__ As,
                                       const float* __restrict__ Bsm,
                                       int ldb, int cbase, int cx, int ty,
                                       const float* __restrict__ bias,
                                       float (&acc)[8][4])
{
    #pragma unroll
    for (int cc = 0; cc < 4; cc++) {
        float bb = bias[cbase + cx * 4 + cc];
        #pragma unroll
        for (int r = 0; r < 8; r++) acc[r][cc] = bb;
    }
    #pragma unroll 4
    for (int k = 0; k < 64; k++) {
        const float4 a0 = *(const float4*)&As[k * 132 + ty * 8];
        const float4 a1 = *(const float4*)&As[k * 132 + ty * 8 + 4];
        const float4 b  = *(const float4*)&Bsm[k * ldb + cbase + cx * 4];
        float av[8] = {a0.x, a0.y, a0.z, a0.w, a1.x, a1.y, a1.z, a1.w};
        float bv[4] = {b.x, b.y, b.z, b.w};
        #pragma unroll
        for (int r = 0; r < 8; r++)
            #pragma unroll
            for (int cc = 0; cc < 4; cc++)
                acc[r][cc] = fmaf(av[r], bv[cc], acc[r][cc]);
    }
}

__device__ __forceinline__ void storeH(float* __restrict__ Hs, int cx, int ty,
                                       const float (&acc)[8][4], bool do_elu)
{
    #pragma unroll
    for (int cc = 0; cc < 4; cc++) {
        int c = cx * 4 + cc;
        float4 v0, v1;
        if (do_elu) {
            v0 = {eluf_(acc[0][cc]), eluf_(acc[1][cc]), eluf_(acc[2][cc]), eluf_(acc[3][cc])};
            v1 = {eluf_(acc[4][cc]), eluf_(acc[5][cc]), eluf_(acc[6][cc]), eluf_(acc[7][cc])};
        } else {
            v0 = {acc[0][cc], acc[1][cc], acc[2][cc], acc[3][cc]};
            v1 = {acc[4][cc], acc[5][cc], acc[6][cc], acc[7][cc]};
        }
        *(float4*)&Hs[c * 132 + ty * 8]     = v0;
        *(float4*)&Hs[c * 132 + ty * 8 + 4] = v1;
    }
}

__global__ void __launch_bounds__(256) kB(
    const float* __restrict__ x,
    const float* __restrict__ vW1, const float* __restrict__ vb1,
    const float* __restrict__ vW2, const float* __restrict__ vb2,
    const float* __restrict__ vWg, const float* __restrict__ vbg,
    const float* __restrict__ vgam, const float* __restrict__ vbet,
    float* __restrict__ out)
{
    extern __shared__ float sm[];
    float* W1s   = sm;             // 4096
    float* W2s   = W1s + 4096;     // 4096
    float* Wgs   = W2s + 4096;     // 8192
    float* Xs    = Wgs + 8192;     // 64*132 = 8448  [k][t]
    float* H1s   = Xs + 8448;      // 8448           [k][t]
    float* H2s   = H1s + 8448;     // 8448           [k][t]
    float* Ps    = H2s + 8448;     // 128*65 = 8320  [t][c]
    float* meanS = Ps + 8320;      // 128
    float* rstdS = meanS + 128;    // 128
    float* wvS   = rstdS + 128;    // 128
    float* b1S   = wvS + 128;      // 64
    float* b2S   = b1S + 64;       // 64
    float* bgS   = b2S + 64;       // 128
    float* gamS  = bgS + 128;      // 64
    float* betS  = gamS + 64;      // 64  -> total 50816 floats = 203,264 B

    const int tid = threadIdx.x;
    const int cx = tid & 15, ty = tid >> 4;
    const int tok0 = blockIdx.x * 128;

    float oacc[8][4];
    #pragma unroll
    for (int r = 0; r < 8; r++)
        #pragma unroll
        for (int cc = 0; cc < 4; cc++) oacc[r][cc] = 0.f;

    for (int v = 0; v < VD; ++v) {
        const float* w1 = vW1 + (size_t)v * 4096;
        const float* w2 = vW2 + (size_t)v * 4096;
        const float* wg = vWg + (size_t)v * 8192;
        #pragma unroll
        for (int p = 0; p < 16; p++) {
            int i = tid + p * 256;
            W1s[i] = w1[i];
            W2s[i] = w2[i];
        }
        #pragma unroll
        for (int p = 0; p < 32; p++) {
            int i = tid + p * 256;
            Wgs[i] = wg[i];
        }
        #pragma unroll
        for (int p = 0; p < 32; p++) {
            int i = tid + p * 256;
            int ii = i & 63, t = i >> 6;
            Xs[ii * 132 + t] = x[(size_t)(tok0 + t) * KF + v * ID + ii];
        }
        if (tid < 64) {
            b1S[tid]  = vb1[(size_t)v * 64 + tid];
            b2S[tid]  = vb2[(size_t)v * 64 + tid];
            gamS[tid] = vgam[(size_t)v * 64 + tid];
            betS[tid] = vbet[(size_t)v * 64 + tid];
        } else if (tid < 192) {
            bgS[tid - 64] = vbg[(size_t)v * 128 + (tid - 64)];
        }
        if (tid < 128) wvS[tid] = g_w[(size_t)(tok0 + tid) * VD + v];
        __syncthreads();

        // GEMM1: H1 = elu(X @ W1 + b1)
        float acc[8][4];
        gemm64(Xs, W1s, 64, 0, cx, ty, b1S, acc);
        storeH(H1s, cx, ty, acc, true);
        __syncthreads();

        // GEMM2: H2 = H1 @ W2 + b2
        gemm64(H1s, W2s, 64, 0, cx, ty, b2S, acc);
        storeH(H2s, cx, ty, acc, false);
        __syncthreads();

        // GEMM3 (fused dual-column): G = H2 @ Wg + bg, cols [c] and [c+64]
        float accL[8][4], accR[8][4];
        #pragma unroll
        for (int cc = 0; cc < 4; cc++) {
            float bL = bgS[cx * 4 + cc];
            float bR = bgS[64 + cx * 4 + cc];
            #pragma unroll
            for (int r = 0; r < 8; r++) { accL[r][cc] = bL; accR[r][cc] = bR; }
        }
        #pragma unroll 2
        for (int k = 0; k < 64; k++) {
            const float4 a0 = *(const float4*)&H2s[k * 132 + ty * 8];
            const float4 a1 = *(const float4*)&H2s[k * 132 + ty * 8 + 4];
            const float4 bL = *(const float4*)&Wgs[k * 128 + cx * 4];
            const float4 bR = *(const float4*)&Wgs[k * 128 + 64 + cx * 4];
            float av[8] = {a0.x, a0.y, a0.z, a0.w, a1.x, a1.y, a1.z, a1.w};
            float bLv[4] = {bL.x, bL.y, bL.z, bL.w};
            float bRv[4] = {bR.x, bR.y, bR.z, bR.w};
            #pragma unroll
            for (int r = 0; r < 8; r++)
                #pragma unroll
                for (int cc = 0; cc < 4; cc++) {
                    accL[r][cc] = fmaf(av[r], bLv[cc], accL[r][cc]);
                    accR[r][cc] = fmaf(av[r], bRv[cc], accR[r][cc]);
                }
        }

        // epilogue: Ps[t][c] = x + a*sigmoid(gate)
        #pragma unroll
        for (int cc = 0; cc < 4; cc++) {
            int c = cx * 4 + cc;
            #pragma unroll
            for (int r = 0; r < 8; r++) {
                int t = ty * 8 + r;
                float xv = Xs[c * 132 + t];
                Ps[t * 65 + c] = xv + accL[r][cc] * sigmoidf_(accR[r][cc]);
            }
        }
        __syncthreads();

        // LN stats (two-pass), one thread per token
        if (tid < 128) {
            float s = 0.f;
            #pragma unroll
            for (int j = 0; j < 64; j++) s += Ps[tid * 65 + j];
            float m = s * (1.f / 64.f);
            float ss = 0.f;
            #pragma unroll
            for (int j = 0; j < 64; j++) { float d = Ps[tid * 65 + j] - m; ss += d * d; }
            meanS[tid] = m;
            rstdS[tid] = rsqrtf(ss * (1.f / 64.f) + 1e-5f);
        }
        __syncthreads();

        // weighted accumulation into register tile
        #pragma unroll
        for (int r = 0; r < 8; r++) {
            int t = ty * 8 + r;
            float wv = wvS[t], m = meanS[t], rs = rstdS[t];
            #pragma unroll
            for (int cc = 0; cc < 4; cc++) {
                int c = cx * 4 + cc;
                float pv = (Ps[t * 65 + c] - m) * rs * gamS[c] + betS[c];
                oacc[r][cc] = fmaf(wv, pv, oacc[r][cc]);
            }
        }
        __syncthreads();
    }

    #pragma unroll
    for (int r = 0; r < 8; r++) {
        float4 o = {oacc[r][0], oacc[r][1], oacc[r][2], oacc[r][3]};
        *(float4*)&out[(size_t)(tok0 + ty * 8 + r) * 64 + cx * 4] = o;
    }
}

extern "C" void kernel_launch(void* const* d_in, const int* in_sizes, int n_in,
                              void* d_out, int out_size)
{
    const float* x     = (const float*)d_in[0];
    const float* wgW1  = (const float*)d_in[1];
    const float* wgb1  = (const float*)d_in[2];
    const float* wgW2  = (const float*)d_in[3];
    const float* wgb2  = (const float*)d_in[4];
    const float* wgWg  = (const float*)d_in[5];
    const float* wgbg  = (const float*)d_in[6];
    const float* wgWs  = (const float*)d_in[7];
    const float* wgbs  = (const float*)d_in[8];
    const float* wggam = (const float*)d_in[9];
    const float* wgbet = (const float*)d_in[10];
    const float* vW1   = (const float*)d_in[11];
    const float* vb1   = (const float*)d_in[12];
    const float* vW2   = (const float*)d_in[13];
    const float* vb2   = (const float*)d_in[14];
    const float* vWg   = (const float*)d_in[15];
    const float* vbg   = (const float*)d_in[16];
    const float* vgam  = (const float*)d_in[17];
    const float* vbet  = (const float*)d_in[18];
    float* out = (float*)d_out;

    int N = in_sizes[0] / KF;  // 32768

    kA1<<<N / 128, 256>>>(x, wgW1, wgb1, wgWs, wgbs);
    kA2<<<(N + 7) / 8, 256>>>(wgW2, wgb2, wgWg, wgbg, wggam, wgbet, N);

    int smB = 50816 * 4;
    cudaFuncSetAttribute(kB, cudaFuncAttributeMaxDynamicSharedMemorySize, smB);
    kB<<<N / 128, 256, smB>>>(x, vW1, vb1, vW2, vb2, vWg, vbg, vgam, vbet, out);
}

// round 2
// speedup vs baseline: 1.0704x; 1.0704x over previous
#include <cuda_runtime.h>
#include <math.h>

#define VD 32
#define ID 64
#define KF 2048
#define NMAX 32768

typedef unsigned long long u64;

// Scratch (device globals: allocation-free rule)
__device__ float g_y[(size_t)NMAX * 64];  // [N,64]: cols 0..31 = flat@W1+b1, cols 32..63 = flat@Ws+bs
__device__ float g_w[(size_t)NMAX * VD];  // softmax weights [N,32]

__device__ __forceinline__ float sigmoidf_(float x) { return 1.f / (1.f + __expf(-x)); }
__device__ __forceinline__ float eluf_(float x) { return x > 0.f ? x : (__expf(x) - 1.f); }

__device__ __forceinline__ float wsum_(float v) {
    #pragma unroll
    for (int o = 16; o > 0; o >>= 1) v += __shfl_xor_sync(0xffffffffu, v, o);
    return v;
}
__device__ __forceinline__ float wmax_(float v) {
    #pragma unroll
    for (int o = 16; o > 0; o >>= 1) v = fmaxf(v, __shfl_xor_sync(0xffffffffu, v, o));
    return v;
}

// ---------------- f32x2 packed-FMA primitives (FFMA2) ----------------
__device__ __forceinline__ u64 ffma2_(u64 a, u64 b, u64 c) {
    u64 d;
    asm("fma.rn.f32x2 %0, %1, %2, %3;" : "=l"(d) : "l"(a), "l"(b), "l"(c));
    return d;
}
__device__ __forceinline__ u64 pack_(float x, float y) {
    u64 r;
    asm("mov.b64 %0, {%1, %2};" : "=l"(r) : "r"(__float_as_uint(x)), "r"(__float_as_uint(y)));
    return r;
}
__device__ __forceinline__ float2 unpack_(u64 v) {
    unsigned lo, hi;
    asm("mov.b64 {%0, %1}, %2;" : "=r"(lo), "=r"(hi) : "l"(v));
    return make_float2(__uint_as_float(lo), __uint_as_float(hi));
}
__device__ __forceinline__ u64 swap_(u64 v) {
    u64 r;
    asm("{\n\t.reg .b32 lo, hi;\n\tmov.b64 {lo, hi}, %1;\n\tmov.b64 %0, {hi, lo};\n\t}"
        : "=l"(r) : "l"(v));
    return r;
}

// Packed 8-row x 4-col accumulator.
// D[rp][cp] = (acc[2rp][2cp],   acc[2rp+1][2cp+1])
// X[rp][cp] = (acc[2rp][2cp+1], acc[2rp+1][2cp])
struct Acc84 { u64 D[4][2]; u64 X[4][2]; };

__device__ __forceinline__ void acc_init4(Acc84& A, const float b4[4]) {
    #pragma unroll
    for (int cp = 0; cp < 2; cp++) {
        u64 d = pack_(b4[2 * cp], b4[2 * cp + 1]);
        u64 x = pack_(b4[2 * cp + 1], b4[2 * cp]);
        #pragma unroll
        for (int rp = 0; rp < 4; rp++) { A.D[rp][cp] = d; A.X[rp][cp] = x; }
    }
}

__device__ __forceinline__ void acc_step(Acc84& A, const u64 a2[4], u64 b0, u64 b1) {
    u64 s0 = swap_(b0), s1 = swap_(b1);
    #pragma unroll
    for (int rp = 0; rp < 4; rp++) {
        A.D[rp][0] = ffma2_(a2[rp], b0, A.D[rp][0]);
        A.X[rp][0] = ffma2_(a2[rp], s0, A.X[rp][0]);
        A.D[rp][1] = ffma2_(a2[rp], b1, A.D[rp][1]);
        A.X[rp][1] = ffma2_(a2[rp], s1, A.X[rp][1]);
    }
}

__device__ __forceinline__ void acc_unpack(const Acc84& A, float (&acc)[8][4]) {
    #pragma unroll
    for (int rp = 0; rp < 4; rp++)
        #pragma unroll
        for (int cp = 0; cp < 2; cp++) {
            float2 dD = unpack_(A.D[rp][cp]);
            float2 dX = unpack_(A.X[rp][cp]);
            acc[2 * rp][2 * cp]         = dD.x;
            acc[2 * rp][2 * cp + 1]     = dX.x;
            acc[2 * rp + 1][2 * cp]     = dX.y;
            acc[2 * rp + 1][2 * cp + 1] = dD.y;
        }
}

// ============================================================
// Kernel A1: Y[N,64] = flat[N,2048] @ [W1 | Ws] + [b1 | bs]
// CTA: 128 tokens x 64 cols; thread: 8 tokens x 4 cols (FFMA2 packed)
// ============================================================
__global__ void __launch_bounds__(256) kA1(
    const float* __restrict__ x,
    const float* __restrict__ W1, const float* __restrict__ b1,
    const float* __restrict__ Ws, const float* __restrict__ bs)
{
    __shared__ float Xs[32 * 132];  // [k][token], pitch 132
    __shared__ float Bs[32 * 64];   // [k][col]

    const int tid = threadIdx.x;
    const int cx = tid & 15, ty = tid >> 4;
    const int tok0 = blockIdx.x * 128;

    Acc84 A;
    {
        float b4[4];
        #pragma unroll
        for (int cc = 0; cc < 4; cc++) {
            int c = cx * 4 + cc;
            b4[cc] = (c < 32) ? b1[c] : bs[c - 32];
        }
        acc_init4(A, b4);
    }

    for (int k0 = 0; k0 < KF; k0 += 32) {
        #pragma unroll
        for (int p = 0; p < 16; p++) {
            int i = tid + p * 256;
            int kk = i & 31, t = i >> 5;
            Xs[kk * 132 + t] = x[(size_t)(tok0 + t) * KF + k0 + kk];
        }
        #pragma unroll
        for (int p = 0; p < 8; p++) {
            int i = tid + p * 256;
            int j = i & 63, kk = i >> 6;
            Bs[kk * 64 + j] = (j < 32) ? W1[(size_t)(k0 + kk) * 32 + j]
                                       : Ws[(size_t)(k0 + kk) * 32 + (j - 32)];
        }
        __syncthreads();

        #pragma unroll 4
        for (int kk = 0; kk < 32; kk++) {
            const ulonglong2 a01 = *(const ulonglong2*)&Xs[kk * 132 + ty * 8];
            const ulonglong2 a23 = *(const ulonglong2*)&Xs[kk * 132 + ty * 8 + 4];
            const ulonglong2 bb  = *(const ulonglong2*)&Bs[kk * 64 + cx * 4];
            u64 a2[4] = {a01.x, a01.y, a23.x, a23.y};
            acc_step(A, a2, bb.x, bb.y);
        }
        __syncthreads();
    }

    float acc[8][4];
    acc_unpack(A, acc);
    #pragma unroll
    for (int r = 0; r < 8; r++) {
        float4 o = {acc[r][0], acc[r][1], acc[r][2], acc[r][3]};
        *(float4*)&g_y[(size_t)(tok0 + ty * 8 + r) * 64 + cx * 4] = o;
    }
}

// ============================================================
// Kernel A2: per-token tail of the weight GRN. One warp = one token.
// ============================================================
__global__ void __launch_bounds__(256) kA2(
    const float* __restrict__ W2, const float* __restrict__ b2,
    const float* __restrict__ Wg, const float* __restrict__ bg,
    const float* __restrict__ gam, const float* __restrict__ bet, int N)
{
    __shared__ float W2s[32 * 33];
    __shared__ float Wgs[32 * 64];
    const int tid = threadIdx.x;
    for (int i = tid; i < 1024; i += 256) W2s[(i >> 5) * 33 + (i & 31)] = W2[i];
    for (int i = tid; i < 2048; i += 256) Wgs[i] = Wg[i];
    __syncthreads();

    const int lane = tid & 31, warp = tid >> 5;
    const int tok = blockIdx.x * 8 + warp;
    if (tok >= N) return;

    const float* y = &g_y[(size_t)tok * 64];
    float hpre = y[lane];
    float skip = y[32 + lane];
    float h = eluf_(hpre);

    float t = b2[lane];
    #pragma unroll
    for (int i = 0; i < 32; i++)
        t = fmaf(__shfl_sync(0xffffffffu, h, i), W2s[i * 33 + lane], t);

    float ga = bg[lane], gb = bg[32 + lane];
    #pragma unroll
    for (int i = 0; i < 32; i++) {
        float tv = __shfl_sync(0xffffffffu, t, i);
        ga = fmaf(tv, Wgs[i * 64 + lane], ga);
        gb = fmaf(tv, Wgs[i * 64 + 32 + lane], gb);
    }

    float z = skip + ga * sigmoidf_(gb);
    float m = wsum_(z) * (1.f / 32.f);
    float d = z - m;
    float var = wsum_(d * d) * (1.f / 32.f);
    float zn = d * rsqrtf(var + 1e-5f) * gam[lane] + bet[lane];

    float mx = wmax_(zn);
    float e = __expf(zn - mx);
    float se = wsum_(e);
    g_w[(size_t)tok * VD + lane] = e / se;
}

// ============================================================
// Kernel B: per-variable GRNs + weighted combine (FFMA2 packed)
// ============================================================
__device__ __forceinline__ void gemm64p(const float* __restrict__ As,
                                        const float* __restrict__ Bsm,
                                        int ldb, int cx, int ty,
                                        const float* __restrict__ bias,
                                        float (&acc)[8][4])
{
    Acc84 A;
    {
        float b4[4];
        #pragma unroll
        for (int cc = 0; cc < 4; cc++) b4[cc] = bias[cx * 4 + cc];
        acc_init4(A, b4);
    }
    #pragma unroll 4
    for (int k = 0; k < 64; k++) {
        const ulonglong2 a01 = *(const ulonglong2*)&As[k * 132 + ty * 8];
        const ulonglong2 a23 = *(const ulonglong2*)&As[k * 132 + ty * 8 + 4];
        const ulonglong2 bb  = *(const ulonglong2*)&Bsm[k * ldb + cx * 4];
        u64 a2[4] = {a01.x, a01.y, a23.x, a23.y};
        acc_step(A, a2, bb.x, bb.y);
    }
    acc_unpack(A, acc);
}

__device__ __forceinline__ void storeH(float* __restrict__ Hs, int cx, int ty,
                                       const float (&acc)[8][4], bool do_elu)
{
    #pragma unroll
    for (int cc = 0; cc < 4; cc++) {
        int c = cx * 4 + cc;
        float4 v0, v1;
        if (do_elu) {
            v0 = {eluf_(acc[0][cc]), eluf_(acc[1][cc]), eluf_(acc[2][cc]), eluf_(acc[3][cc])};
            v1 = {eluf_(acc[4][cc]), eluf_(acc[5][cc]), eluf_(acc[6][cc]), eluf_(acc[7][cc])};
        } else {
            v0 = {acc[0][cc], acc[1][cc], acc[2][cc], acc[3][cc]};
            v1 = {acc[4][cc], acc[5][cc], acc[6][cc], acc[7][cc]};
        }
        *(float4*)&Hs[c * 132 + ty * 8]     = v0;
        *(float4*)&Hs[c * 132 + ty * 8 + 4] = v1;
    }
}

__global__ void __launch_bounds__(256) kB(
    const float* __restrict__ x,
    const float* __restrict__ vW1, const float* __restrict__ vb1,
    const float* __restrict__ vW2, const float* __restrict__ vb2,
    const float* __restrict__ vWg, const float* __restrict__ vbg,
    const float* __restrict__ vgam, const float* __restrict__ vbet,
    float* __restrict__ out)
{
    extern __shared__ float sm[];
    float* W1s   = sm;             // 4096
    float* W2s   = W1s + 4096;     // 4096
    float* Wgs   = W2s + 4096;     // 8192
    float* Xs    = Wgs + 8192;     // 64*132 = 8448  [k][t]
    float* H1s   = Xs + 8448;      // 8448           [k][t]
    float* H2s   = H1s + 8448;     // 8448           [k][t]
    float* Ps    = H2s + 8448;     // 128*65 = 8320  [t][c]
    float* meanS = Ps + 8320;      // 128
    float* rstdS = meanS + 128;    // 128
    float* wvS   = rstdS + 128;    // 128
    float* b1S   = wvS + 128;      // 64
    float* b2S   = b1S + 64;       // 64
    float* bgS   = b2S + 64;       // 128
    float* gamS  = bgS + 128;      // 64
    float* betS  = gamS + 64;      // 64  -> total 50816 floats = 203,264 B

    const int tid = threadIdx.x;
    const int cx = tid & 15, ty = tid >> 4;
    const int tok0 = blockIdx.x * 128;

    float oacc[8][4];
    #pragma unroll
    for (int r = 0; r < 8; r++)
        #pragma unroll
        for (int cc = 0; cc < 4; cc++) oacc[r][cc] = 0.f;

    for (int v = 0; v < VD; ++v) {
        const float* w1 = vW1 + (size_t)v * 4096;
        const float* w2 = vW2 + (size_t)v * 4096;
        const float* wg = vWg + (size_t)v * 8192;
        #pragma unroll
        for (int p = 0; p < 16; p++) {
            int i = tid + p * 256;
            W1s[i] = w1[i];
            W2s[i] = w2[i];
        }
        #pragma unroll
        for (int p = 0; p < 32; p++) {
            int i = tid + p * 256;
            Wgs[i] = wg[i];
        }
        #pragma unroll
        for (int p = 0; p < 32; p++) {
            int i = tid + p * 256;
            int ii = i & 63, t = i >> 6;
            Xs[ii * 132 + t] = x[(size_t)(tok0 + t) * KF + v * ID + ii];
        }
        if (tid < 64) {
            b1S[tid]  = vb1[(size_t)v * 64 + tid];
            b2S[tid]  = vb2[(size_t)v * 64 + tid];
            gamS[tid] = vgam[(size_t)v * 64 + tid];
            betS[tid] = vbet[(size_t)v * 64 + tid];
        } else if (tid < 192) {
            bgS[tid - 64] = vbg[(size_t)v * 128 + (tid - 64)];
        }
        if (tid < 128) wvS[tid] = g_w[(size_t)(tok0 + tid) * VD + v];
        __syncthreads();

        // GEMM1: H1 = elu(X @ W1 + b1)
        float acc[8][4];
        gemm64p(Xs, W1s, 64, cx, ty, b1S, acc);
        storeH(H1s, cx, ty, acc, true);
        __syncthreads();

        // GEMM2: H2 = H1 @ W2 + b2
        gemm64p(H1s, W2s, 64, cx, ty, b2S, acc);
        storeH(H2s, cx, ty, acc, false);
        __syncthreads();

        // GEMM3 (fused dual-column, packed): G = H2 @ Wg + bg, cols [c] and [c+64]
        Acc84 AL, AR;
        {
            float bL4[4], bR4[4];
            #pragma unroll
            for (int cc = 0; cc < 4; cc++) {
                bL4[cc] = bgS[cx * 4 + cc];
                bR4[cc] = bgS[64 + cx * 4 + cc];
            }
            acc_init4(AL, bL4);
            acc_init4(AR, bR4);
        }
        #pragma unroll 2
        for (int k = 0; k < 64; k++) {
            const ulonglong2 a01 = *(const ulonglong2*)&H2s[k * 132 + ty * 8];
            const ulonglong2 a23 = *(const ulonglong2*)&H2s[k * 132 + ty * 8 + 4];
            const ulonglong2 bL  = *(const ulonglong2*)&Wgs[k * 128 + cx * 4];
            const ulonglong2 bR  = *(const ulonglong2*)&Wgs[k * 128 + 64 + cx * 4];
            u64 a2[4] = {a01.x, a01.y, a23.x, a23.y};
            acc_step(AL, a2, bL.x, bL.y);
            acc_step(AR, a2, bR.x, bR.y);
        }
        float accL[8][4], accR[8][4];
        acc_unpack(AL, accL);
        acc_unpack(AR, accR);

        // epilogue: Ps[t][c] = x + a*sigmoid(gate)
        #pragma unroll
        for (int cc = 0; cc < 4; cc++) {
            int c = cx * 4 + cc;
            #pragma unroll
            for (int r = 0; r < 8; r++) {
                int t = ty * 8 + r;
                float xv = Xs[c * 132 + t];
                Ps[t * 65 + c] = xv + accL[r][cc] * sigmoidf_(accR[r][cc]);
            }
        }
        __syncthreads();

        // LN stats (two-pass), one thread per token
        if (tid < 128) {
            float s = 0.f;
            #pragma unroll
            for (int j = 0; j < 64; j++) s += Ps[tid * 65 + j];
            float m = s * (1.f / 64.f);
            float ss = 0.f;
            #pragma unroll
            for (int j = 0; j < 64; j++) { float d = Ps[tid * 65 + j] - m; ss += d * d; }
            meanS[tid] = m;
            rstdS[tid] = rsqrtf(ss * (1.f / 64.f) + 1e-5f);
        }
        __syncthreads();

        // weighted accumulation into register tile
        #pragma unroll
        for (int r = 0; r < 8; r++) {
            int t = ty * 8 + r;
            float wv = wvS[t], m = meanS[t], rs = rstdS[t];
            #pragma unroll
            for (int cc = 0; cc < 4; cc++) {
                int c = cx * 4 + cc;
                float pv = (Ps[t * 65 + c] - m) * rs * gamS[c] + betS[c];
                oacc[r][cc] = fmaf(wv, pv, oacc[r][cc]);
            }
        }
        __syncthreads();
    }

    #pragma unroll
    for (int r = 0; r < 8; r++) {
        float4 o = {oacc[r][0], oacc[r][1], oacc[r][2], oacc[r][3]};
        *(float4*)&out[(size_t)(tok0 + ty * 8 + r) * 64 + cx * 4] = o;
    }
}

extern "C" void kernel_launch(void* const* d_in, const int* in_sizes, int n_in,
                              void* d_out, int out_size)
{
    const float* x     = (const float*)d_in[0];
    const float* wgW1  = (const float*)d_in[1];
    const float* wgb1  = (const float*)d_in[2];
    const float* wgW2  = (const float*)d_in[3];
    const float* wgb2  = (const float*)d_in[4];
    const float* wgWg  = (const float*)d_in[5];
    const float* wgbg  = (const float*)d_in[6];
    const float* wgWs  = (const float*)d_in[7];
    const float* wgbs  = (const float*)d_in[8];
    const float* wggam = (const float*)d_in[9];
    const float* wgbet = (const float*)d_in[10];
    const float* vW1   = (const float*)d_in[11];
    const float* vb1   = (const float*)d_in[12];
    const float* vW2   = (const float*)d_in[13];
    const float* vb2   = (const float*)d_in[14];
    const float* vWg   = (const float*)d_in[15];
    const float* vbg   = (const float*)d_in[16];
    const float* vgam  = (const float*)d_in[17];
    const float* vbet  = (const float*)d_in[18];
    float* out = (float*)d_out;

    int N = in_sizes[0] / KF;  // 32768

    kA1<<<N / 128, 256>>>(x, wgW1, wgb1, wgWs, wgbs);
    kA2<<<(N + 7) / 8, 256>>>(wgW2, wgb2, wgWg, wgbg, wggam, wgbet, N);

    int smB = 50816 * 4;
    cudaFuncSetAttribute(kB, cudaFuncAttributeMaxDynamicSharedMemorySize, smB);
    kB<<<N / 128, 256, smB>>>(x, vW1, vb1, vW2, vb2, vWg, vbg, vgam, vbet, out);
}

// round 4
// speedup vs baseline: 1.8836x; 1.7596x over previous
#include <cuda_runtime.h>
#include <cuda_bf16.h>
#include <math.h>

#define VD 32
#define KF 2048
#define NMAX 32768
#define LDT 72   // smem tile pitch in bf16 elements (64 + 8 pad)

typedef unsigned int u32;
typedef unsigned long long u64;

// ---------------- device scratch (allocation-free rule) ----------------
__device__ float g_y[(size_t)NMAX * 64];
__device__ float g_w[(size_t)NMAX * VD];
// weight B-operand images, [n][k] row-major bf16 hi/lo
__device__ __nv_bfloat16 g_wgBh[64 * 2048];
__device__ __nv_bfloat16 g_wgBl[64 * 2048];
__device__ __nv_bfloat16 g_w1Bh[32 * 64 * 64];
__device__ __nv_bfloat16 g_w1Bl[32 * 64 * 64];
__device__ __nv_bfloat16 g_w2Bh[32 * 64 * 64];
__device__ __nv_bfloat16 g_w2Bl[32 * 64 * 64];
__device__ __nv_bfloat16 g_wgB2h[32 * 128 * 64];
__device__ __nv_bfloat16 g_wgB2l[32 * 128 * 64];

// ---------------- helpers ----------------
__device__ __forceinline__ float sigmoidf_(float x) { return 1.f / (1.f + __expf(-x)); }
__device__ __forceinline__ float eluf_(float x) { return x > 0.f ? x : expm1f(x); }

__device__ __forceinline__ float wsum_(float v) {
    #pragma unroll
    for (int o = 16; o > 0; o >>= 1) v += __shfl_xor_sync(0xffffffffu, v, o);
    return v;
}
__device__ __forceinline__ float wmax_(float v) {
    #pragma unroll
    for (int o = 16; o > 0; o >>= 1) v = fmaxf(v, __shfl_xor_sync(0xffffffffu, v, o));
    return v;
}

// split pair of f32 into packed bf16 hi pair + bf16 lo (residual) pair
__device__ __forceinline__ void split2(float a, float b, u32& hi, u32& lo) {
    __nv_bfloat162 h = __floats2bfloat162_rn(a, b);
    u32 hu = *reinterpret_cast<u32*>(&h);
    float ra = a - __uint_as_float(hu << 16);
    float rb = b - __uint_as_float(hu & 0xffff0000u);
    __nv_bfloat162 l = __floats2bfloat162_rn(ra, rb);
    hi = hu; lo = *reinterpret_cast<u32*>(&l);
}
__device__ __forceinline__ float lo16f_(u32 u) { return __uint_as_float(u << 16); }
__device__ __forceinline__ float hi16f_(u32 u) { return __uint_as_float(u & 0xffff0000u); }

// mma.sync m16n8k16 bf16 -> f32 accumulate (arch-neutral tensor path)
__device__ __forceinline__ void mma_(float (&d)[4], u32 a0, u32 a1, u32 a2, u32 a3,
                                     u32 b0, u32 b1) {
    asm volatile(
        "mma.sync.aligned.m16n8k16.row.col.f32.bf16.bf16.f32 "
        "{%0,%1,%2,%3}, {%4,%5,%6,%7}, {%8,%9}, {%0,%1,%2,%3};"
        : "+f"(d[0]), "+f"(d[1]), "+f"(d[2]), "+f"(d[3])
        : "r"(a0), "r"(a1), "r"(a2), "r"(a3), "r"(b0), "r"(b1));
}

// 3-term K=64 GEMM: acc += Ah*Bh + Ah*Bl + Al*Bh. A,B tiles in smem (bf16, pitch LDT).
// Passes over n-tiles keep same-acc reuse distance >= NT.
template<int NT>
__device__ __forceinline__ void gemm3(const char* sm, int AHI, int ALO, int BHI, int BLO,
                                      int r0, int g, int tg, float (&acc)[NT][4]) {
    #pragma unroll
    for (int ks = 0; ks < 4; ks++) {
        int ao = ks * 16 + tg * 2;
        u32 ah0 = *(const u32*)(sm + AHI + ((r0 + g) * LDT + ao) * 2);
        u32 ah1 = *(const u32*)(sm + AHI + ((r0 + g + 8) * LDT + ao) * 2);
        u32 ah2 = *(const u32*)(sm + AHI + ((r0 + g) * LDT + ao + 8) * 2);
        u32 ah3 = *(const u32*)(sm + AHI + ((r0 + g + 8) * LDT + ao + 8) * 2);
        u32 al0 = *(const u32*)(sm + ALO + ((r0 + g) * LDT + ao) * 2);
        u32 al1 = *(const u32*)(sm + ALO + ((r0 + g + 8) * LDT + ao) * 2);
        u32 al2 = *(const u32*)(sm + ALO + ((r0 + g) * LDT + ao + 8) * 2);
        u32 al3 = *(const u32*)(sm + ALO + ((r0 + g + 8) * LDT + ao + 8) * 2);
        #pragma unroll
        for (int nt = 0; nt < NT; nt++) {
            u32 b0 = *(const u32*)(sm + BHI + ((nt * 8 + g) * LDT + ao) * 2);
            u32 b1 = *(const u32*)(sm + BHI + ((nt * 8 + g) * LDT + ao + 8) * 2);
            mma_(acc[nt], ah0, ah1, ah2, ah3, b0, b1);
        }
        #pragma unroll
        for (int nt = 0; nt < NT; nt++) {
            u32 b0 = *(const u32*)(sm + BLO + ((nt * 8 + g) * LDT + ao) * 2);
            u32 b1 = *(const u32*)(sm + BLO + ((nt * 8 + g) * LDT + ao + 8) * 2);
            mma_(acc[nt], ah0, ah1, ah2, ah3, b0, b1);
        }
        #pragma unroll
        for (int nt = 0; nt < NT; nt++) {
            u32 b0 = *(const u32*)(sm + BHI + ((nt * 8 + g) * LDT + ao) * 2);
            u32 b1 = *(const u32*)(sm + BHI + ((nt * 8 + g) * LDT + ao + 8) * 2);
            mma_(acc[nt], al0, al1, al2, al3, b0, b1);
        }
    }
}

// stage 128x64 fp32 -> smem bf16 hi/lo tiles (split in flight)
__device__ __forceinline__ void stage_x_split(char* sm, int HIo, int LOo,
        const float* __restrict__ x, int tok0, int kbase, int tid) {
    #pragma unroll
    for (int p = 0; p < 8; p++) {
        int idx = tid + p * 256;
        int row = idx >> 4, c4 = (idx & 15) * 4;
        float4 f = *(const float4*)&x[(size_t)(tok0 + row) * KF + kbase + c4];
        u32 h0, l0, h1, l1;
        split2(f.x, f.y, h0, l0); split2(f.z, f.w, h1, l1);
        *(uint2*)(sm + HIo + (row * LDT + c4) * 2) = make_uint2(h0, h1);
        *(uint2*)(sm + LOo + (row * LDT + c4) * 2) = make_uint2(l0, l1);
    }
}

// stage 64x64 bf16 weight tile (padded pitch)
__device__ __forceinline__ void stage_w64(char* sm, int DSTo,
        const __nv_bfloat16* __restrict__ src, int pitch, int tid) {
    int row = tid >> 2, part = tid & 3;
    #pragma unroll
    for (int q = 0; q < 2; q++) {
        int col = (part * 2 + q) * 8;
        uint4 v = *(const uint4*)&src[(size_t)row * pitch + col];
        *(uint4*)(sm + DSTo + (row * LDT + col) * 2) = v;
    }
}

// stage 128x64 bf16 weight tile
__device__ __forceinline__ void stage_w128(char* sm, int DSTo,
        const __nv_bfloat16* __restrict__ src, int tid) {
    int row = tid >> 1, part = tid & 1;
    #pragma unroll
    for (int q = 0; q < 4; q++) {
        int col = (part * 4 + q) * 8;
        uint4 v = *(const uint4*)&src[(size_t)row * 64 + col];
        *(uint4*)(sm + DSTo + (row * LDT + col) * 2) = v;
    }
}

// store warp fragments (+bias, opt elu), split to bf16 hi/lo tiles
__device__ __forceinline__ void store_split(char* sm, int HIo, int LOo,
        int r0, int g, int tg, const float (&acc)[8][4],
        const float* __restrict__ bias, bool do_elu) {
    #pragma unroll
    for (int nt = 0; nt < 8; nt++) {
        int c = nt * 8 + tg * 2;
        float f0 = acc[nt][0] + bias[c], f1 = acc[nt][1] + bias[c + 1];
        float f2 = acc[nt][2] + bias[c], f3 = acc[nt][3] + bias[c + 1];
        if (do_elu) { f0 = eluf_(f0); f1 = eluf_(f1); f2 = eluf_(f2); f3 = eluf_(f3); }
        u32 h, l;
        split2(f0, f1, h, l);
        *(u32*)(sm + HIo + ((r0 + g) * LDT + c) * 2) = h;
        *(u32*)(sm + LOo + ((r0 + g) * LDT + c) * 2) = l;
        split2(f2, f3, h, l);
        *(u32*)(sm + HIo + ((r0 + g + 8) * LDT + c) * 2) = h;
        *(u32*)(sm + LOo + ((r0 + g + 8) * LDT + c) * 2) = l;
    }
}

// ============================================================
// kPrepW: transpose + split all weight B-operands to [n][k] bf16 hi/lo
// ============================================================
__device__ __forceinline__ void store8(__nv_bfloat16* hiA, __nv_bfloat16* loA,
                                       size_t base, const float f[8]) {
    u32 h[4], l[4];
    #pragma unroll
    for (int p = 0; p < 4; p++) split2(f[2 * p], f[2 * p + 1], h[p], l[p]);
    *(uint4*)&hiA[base] = make_uint4(h[0], h[1], h[2], h[3]);
    *(uint4*)&loA[base] = make_uint4(l[0], l[1], l[2], l[3]);
}

__global__ void __launch_bounds__(256) kPrepW(
    const float* __restrict__ wgW1, const float* __restrict__ wgWs,
    const float* __restrict__ vW1, const float* __restrict__ vW2,
    const float* __restrict__ vWg) {
    int id = blockIdx.x * 256 + threadIdx.x;
    float f[8];
    if (id < 16384) {                    // wgB: [64 n][2048 k]
        int j = id & 7, n = (id >> 3) & 63, c = id >> 9;
        int k0 = c * 64 + j * 8;
        #pragma unroll
        for (int kk = 0; kk < 8; kk++)
            f[kk] = (n < 32) ? wgW1[(size_t)(k0 + kk) * 32 + n]
                             : wgWs[(size_t)(k0 + kk) * 32 + (n - 32)];
        store8(g_wgBh, g_wgBl, (size_t)n * 2048 + k0, f);
    } else if (id < 32768) {             // vW1: [v][64 n][64 k]
        id -= 16384;
        int j = id & 7, n = (id >> 3) & 63, v = id >> 9;
        #pragma unroll
        for (int kk = 0; kk < 8; kk++)
            f[kk] = vW1[((size_t)v * 64 + j * 8 + kk) * 64 + n];
        store8(g_w1Bh, g_w1Bl, ((size_t)v * 64 + n) * 64 + j * 8, f);
    } else if (id < 49152) {             // vW2
        id -= 32768;
        int j = id & 7, n = (id >> 3) & 63, v = id >> 9;
        #pragma unroll
        for (int kk = 0; kk < 8; kk++)
            f[kk] = vW2[((size_t)v * 64 + j * 8 + kk) * 64 + n];
        store8(g_w2Bh, g_w2Bl, ((size_t)v * 64 + n) * 64 + j * 8, f);
    } else if (id < 81920) {             // vWg: [v][128 n][64 k]
        id -= 49152;
        int j = id & 7, n = (id >> 3) & 127, v = id >> 10;
        #pragma unroll
        for (int kk = 0; kk < 8; kk++)
            f[kk] = vWg[((size_t)v * 64 + j * 8 + kk) * 128 + n];
        store8(g_wgB2h, g_wgB2l, ((size_t)v * 128 + n) * 64 + j * 8, f);
    }
}

// ============================================================
// kA1m: Y[N,64] = flat[N,2048] @ [W1|Ws] (+bias) via mma.sync -> g_y
// ============================================================
#define A1_XHI 0
#define A1_XLO 18432
#define A1_BH  36864
#define A1_BL  46080
#define A1_SMEM 55296

__global__ void __launch_bounds__(256) kA1m(
    const float* __restrict__ x, const float* __restrict__ b1,
    const float* __restrict__ bs) {
    extern __shared__ __align__(16) char sm[];
    const int tid = threadIdx.x, lane = tid & 31;
    const int warp = tid >> 5, g = lane >> 2, tg = lane & 3;
    const int r0 = warp * 16, tok0 = blockIdx.x * 128;

    float acc[8][4];
    #pragma unroll
    for (int nt = 0; nt < 8; nt++)
        acc[nt][0] = acc[nt][1] = acc[nt][2] = acc[nt][3] = 0.f;

    for (int kc = 0; kc < 32; kc++) {
        stage_x_split(sm, A1_XHI, A1_XLO, x, tok0, kc * 64, tid);
        stage_w64(sm, A1_BH, g_wgBh + kc * 64, 2048, tid);
        stage_w64(sm, A1_BL, g_wgBl + kc * 64, 2048, tid);
        __syncthreads();
        gemm3<8>(sm, A1_XHI, A1_XLO, A1_BH, A1_BL, r0, g, tg, acc);
        __syncthreads();
    }

    #pragma unroll
    for (int nt = 0; nt < 8; nt++) {
        int c = nt * 8 + tg * 2;
        float bb0 = (c < 32) ? b1[c] : bs[c - 32];
        float bb1 = (c + 1 < 32) ? b1[c + 1] : bs[c + 1 - 32];
        float* yA = &g_y[(size_t)(tok0 + r0 + g) * 64 + c];
        float* yB = &g_y[(size_t)(tok0 + r0 + g + 8) * 64 + c];
        yA[0] = acc[nt][0] + bb0; yA[1] = acc[nt][1] + bb1;
        yB[0] = acc[nt][2] + bb0; yB[1] = acc[nt][3] + bb1;
    }
}

// ============================================================
// kA2: per-token tail of the weight GRN (fp32, cheap)
// ============================================================
__global__ void __launch_bounds__(256) kA2(
    const float* __restrict__ W2, const float* __restrict__ b2,
    const float* __restrict__ Wg, const float* __restrict__ bg,
    const float* __restrict__ gam, const float* __restrict__ bet, int N) {
    __shared__ float W2s[32 * 33];
    __shared__ float Wgs[32 * 64];
    const int tid = threadIdx.x;
    for (int i = tid; i < 1024; i += 256) W2s[(i >> 5) * 33 + (i & 31)] = W2[i];
    for (int i = tid; i < 2048; i += 256) Wgs[i] = Wg[i];
    __syncthreads();

    const int lane = tid & 31, warp = tid >> 5;
    const int tok = blockIdx.x * 8 + warp;
    if (tok >= N) return;

    const float* y = &g_y[(size_t)tok * 64];
    float h = eluf_(y[lane]);
    float skip = y[32 + lane];

    float t = b2[lane];
    #pragma unroll
    for (int i = 0; i < 32; i++)
        t = fmaf(__shfl_sync(0xffffffffu, h, i), W2s[i * 33 + lane], t);

    float ga = bg[lane], gb = bg[32 + lane];
    #pragma unroll
    for (int i = 0; i < 32; i++) {
        float tv = __shfl_sync(0xffffffffu, t, i);
        ga = fmaf(tv, Wgs[i * 64 + lane], ga);
        gb = fmaf(tv, Wgs[i * 64 + 32 + lane], gb);
    }

    float z = skip + ga * sigmoidf_(gb);
    float m = wsum_(z) * (1.f / 32.f);
    float d = z - m;
    float var = wsum_(d * d) * (1.f / 32.f);
    float zn = d * rsqrtf(var + 1e-5f) * gam[lane] + bet[lane];

    float mx = wmax_(zn);
    float e = __expf(zn - mx);
    float se = wsum_(e);
    g_w[(size_t)tok * VD + lane] = e / se;
}

// ============================================================
// kBm: per-variable GRNs + weighted combine, all GEMMs via mma.sync
// ============================================================
#define KB_XHI  0
#define KB_XLO  18432
#define KB_W1H  36864
#define KB_W1L  46080
#define KB_W2H  55296
#define KB_W2L  64512
#define KB_WGH  73728
#define KB_WGL  92160
#define KB_H1H  110592
#define KB_H1L  129024
#define KB_H2H  147456
#define KB_H2L  165888
#define KB_BIAS 184320
#define KB_SMEM (184320 + 2048)

__global__ void __launch_bounds__(256) kBm(
    const float* __restrict__ x,
    const float* __restrict__ vb1, const float* __restrict__ vb2,
    const float* __restrict__ vbg, const float* __restrict__ vgam,
    const float* __restrict__ vbet, float* __restrict__ out) {
    extern __shared__ __align__(16) char sm[];
    float* b1s  = (float*)(sm + KB_BIAS);        // 64
    float* b2s  = b1s + 64;                      // 64
    float* bgs  = b2s + 64;                      // 128
    float* gams = bgs + 128;                     // 64
    float* bets = gams + 64;                     // 64
    float* wvS  = bets + 64;                     // 128

    const int tid = threadIdx.x, lane = tid & 31;
    const int warp = tid >> 5, g = lane >> 2, tg = lane & 3;
    const int r0 = warp * 16, tok0 = blockIdx.x * 128;

    float oacc[2][16];
    #pragma unroll
    for (int s = 0; s < 2; s++)
        #pragma unroll
        for (int i = 0; i < 16; i++) oacc[s][i] = 0.f;

    for (int v = 0; v < VD; v++) {
        // ---- stage ----
        stage_x_split(sm, KB_XHI, KB_XLO, x, tok0, v * 64, tid);
        stage_w64(sm, KB_W1H, g_w1Bh + (size_t)v * 4096, 64, tid);
        stage_w64(sm, KB_W1L, g_w1Bl + (size_t)v * 4096, 64, tid);
        stage_w64(sm, KB_W2H, g_w2Bh + (size_t)v * 4096, 64, tid);
        stage_w64(sm, KB_W2L, g_w2Bl + (size_t)v * 4096, 64, tid);
        stage_w128(sm, KB_WGH, g_wgB2h + (size_t)v * 8192, tid);
        stage_w128(sm, KB_WGL, g_wgB2l + (size_t)v * 8192, tid);
        if (tid < 64) {
            b1s[tid]  = vb1[(size_t)v * 64 + tid];
            b2s[tid]  = vb2[(size_t)v * 64 + tid];
            gams[tid] = vgam[(size_t)v * 64 + tid];
            bets[tid] = vbet[(size_t)v * 64 + tid];
        } else if (tid < 192) {
            bgs[tid - 64] = vbg[(size_t)v * 128 + (tid - 64)];
        }
        if (tid < 128) wvS[tid] = g_w[(size_t)(tok0 + tid) * VD + v];
        __syncthreads();

        // ---- GEMM1: H1 = elu(X @ W1 + b1) ----
        {
            float acc[8][4];
            #pragma unroll
            for (int nt = 0; nt < 8; nt++)
                acc[nt][0] = acc[nt][1] = acc[nt][2] = acc[nt][3] = 0.f;
            gemm3<8>(sm, KB_XHI, KB_XLO, KB_W1H, KB_W1L, r0, g, tg, acc);
            store_split(sm, KB_H1H, KB_H1L, r0, g, tg, acc, b1s, true);
        }
        __syncthreads();

        // ---- GEMM2: H2 = H1 @ W2 + b2 ----
        {
            float acc[8][4];
            #pragma unroll
            for (int nt = 0; nt < 8; nt++)
                acc[nt][0] = acc[nt][1] = acc[nt][2] = acc[nt][3] = 0.f;
            gemm3<8>(sm, KB_H1H, KB_H1L, KB_W2H, KB_W2L, r0, g, tg, acc);
            store_split(sm, KB_H2H, KB_H2L, r0, g, tg, acc, b2s, false);
        }
        __syncthreads();

        // ---- GEMM3: G = H2 @ Wg (N=128) + epilogue ----
        {
            float acc3[16][4];
            #pragma unroll
            for (int nt = 0; nt < 16; nt++)
                acc3[nt][0] = acc3[nt][1] = acc3[nt][2] = acc3[nt][3] = 0.f;
            gemm3<16>(sm, KB_H2H, KB_H2L, KB_WGH, KB_WGL, r0, g, tg, acc3);

            #pragma unroll
            for (int sel = 0; sel < 2; sel++) {
                const int row = r0 + g + sel * 8;
                const int di = sel * 2;
                float vals[16];
                float s1 = 0.f, s2 = 0.f;
                #pragma unroll
                for (int i = 0; i < 8; i++) {
                    int c = i * 8 + tg * 2;
                    u32 xh = *(const u32*)(sm + KB_XHI + (row * LDT + c) * 2);
                    u32 xl = *(const u32*)(sm + KB_XLO + (row * LDT + c) * 2);
                    float x0 = lo16f_(xh) + lo16f_(xl);
                    float x1 = hi16f_(xh) + hi16f_(xl);
                    float aL = acc3[i][di] + bgs[c];
                    float aR = acc3[i][di + 1] + bgs[c + 1];
                    float gL = acc3[8 + i][di] + bgs[64 + c];
                    float gR = acc3[8 + i][di + 1] + bgs[64 + c + 1];
                    float v0 = x0 + aL * sigmoidf_(gL);
                    float v1 = x1 + aR * sigmoidf_(gR);
                    vals[2 * i] = v0; vals[2 * i + 1] = v1;
                    s1 += v0 + v1;
                    s2 += v0 * v0 + v1 * v1;
                }
                s1 += __shfl_xor_sync(0xffffffffu, s1, 1);
                s1 += __shfl_xor_sync(0xffffffffu, s1, 2);
                s2 += __shfl_xor_sync(0xffffffffu, s2, 1);
                s2 += __shfl_xor_sync(0xffffffffu, s2, 2);
                float m = s1 * (1.f / 64.f);
                float var = fmaxf(s2 * (1.f / 64.f) - m * m, 0.f);
                float rs = rsqrtf(var + 1e-5f);
                float wv = wvS[row];
                #pragma unroll
                for (int i = 0; i < 8; i++) {
                    int c = i * 8 + tg * 2;
                    float pv0 = (vals[2 * i] - m) * rs * gams[c] + bets[c];
                    float pv1 = (vals[2 * i + 1] - m) * rs * gams[c + 1] + bets[c + 1];
                    oacc[sel][2 * i]     = fmaf(wv, pv0, oacc[sel][2 * i]);
                    oacc[sel][2 * i + 1] = fmaf(wv, pv1, oacc[sel][2 * i + 1]);
                }
            }
        }
        __syncthreads();   // protect smem before next stage
    }

    #pragma unroll
    for (int sel = 0; sel < 2; sel++) {
        int row = r0 + g + sel * 8;
        float* op = &out[(size_t)(tok0 + row) * 64];
        #pragma unroll
        for (int i = 0; i < 8; i++) {
            int c = i * 8 + tg * 2;
            *(float2*)&op[c] = make_float2(oacc[sel][2 * i], oacc[sel][2 * i + 1]);
        }
    }
}

// ============================================================
extern "C" void kernel_launch(void* const* d_in, const int* in_sizes, int n_in,
                              void* d_out, int out_size) {
    const float* x     = (const float*)d_in[0];
    const float* wgW1  = (const float*)d_in[1];
    const float* wgb1  = (const float*)d_in[2];
    const float* wgW2  = (const float*)d_in[3];
    const float* wgb2  = (const float*)d_in[4];
    const float* wgWg  = (const float*)d_in[5];
    const float* wgbg  = (const float*)d_in[6];
    const float* wgWs  = (const float*)d_in[7];
    const float* wgbs  = (const float*)d_in[8];
    const float* wggam = (const float*)d_in[9];
    const float* wgbet = (const float*)d_in[10];
    const float* vW1   = (const float*)d_in[11];
    const float* vb1   = (const float*)d_in[12];
    const float* vW2   = (const float*)d_in[13];
    const float* vb2   = (const float*)d_in[14];
    const float* vWg   = (const float*)d_in[15];
    const float* vbg   = (const float*)d_in[16];
    const float* vgam  = (const float*)d_in[17];
    const float* vbet  = (const float*)d_in[18];
    float* out = (float*)d_out;

    int N = in_sizes[0] / KF;  // 32768

    kPrepW<<<320, 256>>>(wgW1, wgWs, vW1, vW2, vWg);

    cudaFuncSetAttribute(kA1m, cudaFuncAttributeMaxDynamicSharedMemorySize, A1_SMEM);
    kA1m<<<N / 128, 256, A1_SMEM>>>(x, wgb1, wgbs);

    kA2<<<(N + 7) / 8, 256>>>(wgW2, wgb2, wgWg, wgbg, wggam, wgbet, N);

    cudaFuncSetAttribute(kBm, cudaFuncAttributeMaxDynamicSharedMemorySize, KB_SMEM);
    kBm<<<N / 128, 256, KB_SMEM>>>(x, vb1, vb2, vbg, vgam, vbet, out);
}

// round 5
// speedup vs baseline: 3.0516x; 1.6201x over previous
#include <cuda_runtime.h>
#include <cuda_bf16.h>
#include <math.h>

#define VD 32
#define KF 2048
#define NMAX 32768
#define LDT 72   // smem tile pitch in bf16 elements (64 + 8 pad) — conflict-free

typedef unsigned int u32;
typedef unsigned long long u64;

// ---------------- device scratch (allocation-free rule) ----------------
__device__ float g_y[(size_t)NMAX * 64];
__device__ float g_w[(size_t)NMAX * VD];
// weight B-operand images, [n][k] row-major bf16 hi/lo
__device__ __nv_bfloat16 g_wgBh[64 * 2048];
__device__ __nv_bfloat16 g_wgBl[64 * 2048];
__device__ __nv_bfloat16 g_w1Bh[32 * 64 * 64];
__device__ __nv_bfloat16 g_w2Bh[32 * 64 * 64];
__device__ __nv_bfloat16 g_wgB2h[32 * 128 * 64];

// ---------------- helpers ----------------
__device__ __forceinline__ float sigmoidf_(float x) { return 1.f / (1.f + __expf(-x)); }
__device__ __forceinline__ float eluf_(float x) { return x > 0.f ? x : expm1f(x); }

__device__ __forceinline__ float wsum_(float v) {
    #pragma unroll
    for (int o = 16; o > 0; o >>= 1) v += __shfl_xor_sync(0xffffffffu, v, o);
    return v;
}
__device__ __forceinline__ float wmax_(float v) {
    #pragma unroll
    for (int o = 16; o > 0; o >>= 1) v = fmaxf(v, __shfl_xor_sync(0xffffffffu, v, o));
    return v;
}

// split pair of f32 into packed bf16 hi pair + bf16 lo (residual) pair
__device__ __forceinline__ void split2(float a, float b, u32& hi, u32& lo) {
    __nv_bfloat162 h = __floats2bfloat162_rn(a, b);
    u32 hu = *reinterpret_cast<u32*>(&h);
    float ra = a - __uint_as_float(hu << 16);
    float rb = b - __uint_as_float(hu & 0xffff0000u);
    __nv_bfloat162 l = __floats2bfloat162_rn(ra, rb);
    hi = hu; lo = *reinterpret_cast<u32*>(&l);
}
__device__ __forceinline__ u32 pack_bf2(float a, float b) {
    __nv_bfloat162 h = __floats2bfloat162_rn(a, b);
    return *reinterpret_cast<u32*>(&h);
}
__device__ __forceinline__ float lo16f_(u32 u) { return __uint_as_float(u << 16); }
__device__ __forceinline__ float hi16f_(u32 u) { return __uint_as_float(u & 0xffff0000u); }

// mma.sync m16n8k16 bf16 -> f32 accumulate
__device__ __forceinline__ void mma_(float (&d)[4], u32 a0, u32 a1, u32 a2, u32 a3,
                                     u32 b0, u32 b1) {
    asm volatile(
        "mma.sync.aligned.m16n8k16.row.col.f32.bf16.bf16.f32 "
        "{%0,%1,%2,%3}, {%4,%5,%6,%7}, {%8,%9}, {%0,%1,%2,%3};"
        : "+f"(d[0]), "+f"(d[1]), "+f"(d[2]), "+f"(d[3])
        : "r"(a0), "r"(a1), "r"(a2), "r"(a3), "r"(b0), "r"(b1));
}

// single-term K=64 GEMM: acc += A*B (bf16 tiles, pitch LDT)
template<int NT>
__device__ __forceinline__ void gemm1t(const char* sm, int Aof, int Bof,
                                       int r0, int g, int tg, float (&acc)[NT][4]) {
    #pragma unroll
    for (int ks = 0; ks < 4; ks++) {
        int ao = ks * 16 + tg * 2;
        u32 a0 = *(const u32*)(sm + Aof + ((r0 + g) * LDT + ao) * 2);
        u32 a1 = *(const u32*)(sm + Aof + ((r0 + g + 8) * LDT + ao) * 2);
        u32 a2 = *(const u32*)(sm + Aof + ((r0 + g) * LDT + ao + 8) * 2);
        u32 a3 = *(const u32*)(sm + Aof + ((r0 + g + 8) * LDT + ao + 8) * 2);
        #pragma unroll
        for (int nt = 0; nt < NT; nt++) {
            u32 b0 = *(const u32*)(sm + Bof + ((nt * 8 + g) * LDT + ao) * 2);
            u32 b1 = *(const u32*)(sm + Bof + ((nt * 8 + g) * LDT + ao + 8) * 2);
            mma_(acc[nt], a0, a1, a2, a3, b0, b1);
        }
    }
}

// 3-term K=64 GEMM (hi/lo): acc += Ah*Bh + Ah*Bl + Al*Bh
template<int NT>
__device__ __forceinline__ void gemm3(const char* sm, int AHI, int ALO, int BHI, int BLO,
                                      int r0, int g, int tg, float (&acc)[NT][4]) {
    #pragma unroll
    for (int ks = 0; ks < 4; ks++) {
        int ao = ks * 16 + tg * 2;
        u32 ah0 = *(const u32*)(sm + AHI + ((r0 + g) * LDT + ao) * 2);
        u32 ah1 = *(const u32*)(sm + AHI + ((r0 + g + 8) * LDT + ao) * 2);
        u32 ah2 = *(const u32*)(sm + AHI + ((r0 + g) * LDT + ao + 8) * 2);
        u32 ah3 = *(const u32*)(sm + AHI + ((r0 + g + 8) * LDT + ao + 8) * 2);
        u32 al0 = *(const u32*)(sm + ALO + ((r0 + g) * LDT + ao) * 2);
        u32 al1 = *(const u32*)(sm + ALO + ((r0 + g + 8) * LDT + ao) * 2);
        u32 al2 = *(const u32*)(sm + ALO + ((r0 + g) * LDT + ao + 8) * 2);
        u32 al3 = *(const u32*)(sm + ALO + ((r0 + g + 8) * LDT + ao + 8) * 2);
        #pragma unroll
        for (int nt = 0; nt < NT; nt++) {
            u32 b0 = *(const u32*)(sm + BHI + ((nt * 8 + g) * LDT + ao) * 2);
            u32 b1 = *(const u32*)(sm + BHI + ((nt * 8 + g) * LDT + ao + 8) * 2);
            mma_(acc[nt], ah0, ah1, ah2, ah3, b0, b1);
        }
        #pragma unroll
        for (int nt = 0; nt < NT; nt++) {
            u32 b0 = *(const u32*)(sm + BLO + ((nt * 8 + g) * LDT + ao) * 2);
            u32 b1 = *(const u32*)(sm + BLO + ((nt * 8 + g) * LDT + ao + 8) * 2);
            mma_(acc[nt], ah0, ah1, ah2, ah3, b0, b1);
        }
        #pragma unroll
        for (int nt = 0; nt < NT; nt++) {
            u32 b0 = *(const u32*)(sm + BHI + ((nt * 8 + g) * LDT + ao) * 2);
            u32 b1 = *(const u32*)(sm + BHI + ((nt * 8 + g) * LDT + ao + 8) * 2);
            mma_(acc[nt], al0, al1, al2, al3, b0, b1);
        }
    }
}

// stage 128x64 fp32 -> smem bf16 hi/lo tiles
__device__ __forceinline__ void stage_x_split(char* sm, int HIo, int LOo,
        const float* __restrict__ x, int tok0, int kbase, int tid) {
    #pragma unroll
    for (int p = 0; p < 8; p++) {
        int idx = tid + p * 256;
        int row = idx >> 4, c4 = (idx & 15) * 4;
        float4 f = *(const float4*)&x[(size_t)(tok0 + row) * KF + kbase + c4];
        u32 h0, l0, h1, l1;
        split2(f.x, f.y, h0, l0); split2(f.z, f.w, h1, l1);
        *(uint2*)(sm + HIo + (row * LDT + c4) * 2) = make_uint2(h0, h1);
        *(uint2*)(sm + LOo + (row * LDT + c4) * 2) = make_uint2(l0, l1);
    }
}

// stage 64x64 bf16 weight tile (padded pitch)
__device__ __forceinline__ void stage_w64(char* sm, int DSTo,
        const __nv_bfloat16* __restrict__ src, int pitch, int tid) {
    int row = tid >> 2, part = tid & 3;
    #pragma unroll
    for (int q = 0; q < 2; q++) {
        int col = (part * 2 + q) * 8;
        uint4 v = *(const uint4*)&src[(size_t)row * pitch + col];
        *(uint4*)(sm + DSTo + (row * LDT + col) * 2) = v;
    }
}

// stage 128x64 bf16 weight tile
__device__ __forceinline__ void stage_w128(char* sm, int DSTo,
        const __nv_bfloat16* __restrict__ src, int tid) {
    int row = tid >> 1, part = tid & 1;
    #pragma unroll
    for (int q = 0; q < 4; q++) {
        int col = (part * 4 + q) * 8;
        uint4 v = *(const uint4*)&src[(size_t)row * 64 + col];
        *(uint4*)(sm + DSTo + (row * LDT + col) * 2) = v;
    }
}

// store warp fragments (+bias, opt elu) as single bf16 tile
__device__ __forceinline__ void store_bf(char* sm, int Hof,
        int r0, int g, int tg, const float (&acc)[8][4],
        const float* __restrict__ bias, bool do_elu) {
    #pragma unroll
    for (int nt = 0; nt < 8; nt++) {
        int c = nt * 8 + tg * 2;
        float f0 = acc[nt][0] + bias[c], f1 = acc[nt][1] + bias[c + 1];
        float f2 = acc[nt][2] + bias[c], f3 = acc[nt][3] + bias[c + 1];
        if (do_elu) { f0 = eluf_(f0); f1 = eluf_(f1); f2 = eluf_(f2); f3 = eluf_(f3); }
        *(u32*)(sm + Hof + ((r0 + g) * LDT + c) * 2) = pack_bf2(f0, f1);
        *(u32*)(sm + Hof + ((r0 + g + 8) * LDT + c) * 2) = pack_bf2(f2, f3);
    }
}

// ============================================================
// kPrepW: transpose + split all weight B-operands to [n][k] bf16
// ============================================================
__device__ __forceinline__ void store8hl(__nv_bfloat16* hiA, __nv_bfloat16* loA,
                                         size_t base, const float f[8]) {
    u32 h[4], l[4];
    #pragma unroll
    for (int p = 0; p < 4; p++) split2(f[2 * p], f[2 * p + 1], h[p], l[p]);
    *(uint4*)&hiA[base] = make_uint4(h[0], h[1], h[2], h[3]);
    *(uint4*)&loA[base] = make_uint4(l[0], l[1], l[2], l[3]);
}
__device__ __forceinline__ void store8h(__nv_bfloat16* hiA, size_t base, const float f[8]) {
    u32 h[4];
    #pragma unroll
    for (int p = 0; p < 4; p++) h[p] = pack_bf2(f[2 * p], f[2 * p + 1]);
    *(uint4*)&hiA[base] = make_uint4(h[0], h[1], h[2], h[3]);
}

__global__ void __launch_bounds__(256) kPrepW(
    const float* __restrict__ wgW1, const float* __restrict__ wgWs,
    const float* __restrict__ vW1, const float* __restrict__ vW2,
    const float* __restrict__ vWg) {
    int id = blockIdx.x * 256 + threadIdx.x;
    float f[8];
    if (id < 16384) {                    // wgB: [64 n][2048 k] hi/lo
        int j = id & 7, n = (id >> 3) & 63, c = id >> 9;
        int k0 = c * 64 + j * 8;
        #pragma unroll
        for (int kk = 0; kk < 8; kk++)
            f[kk] = (n < 32) ? wgW1[(size_t)(k0 + kk) * 32 + n]
                             : wgWs[(size_t)(k0 + kk) * 32 + (n - 32)];
        store8hl(g_wgBh, g_wgBl, (size_t)n * 2048 + k0, f);
    } else if (id < 32768) {             // vW1: [v][64 n][64 k]
        id -= 16384;
        int j = id & 7, n = (id >> 3) & 63, v = id >> 9;
        #pragma unroll
        for (int kk = 0; kk < 8; kk++)
            f[kk] = vW1[((size_t)v * 64 + j * 8 + kk) * 64 + n];
        store8h(g_w1Bh, ((size_t)v * 64 + n) * 64 + j * 8, f);
    } else if (id < 49152) {             // vW2
        id -= 32768;
        int j = id & 7, n = (id >> 3) & 63, v = id >> 9;
        #pragma unroll
        for (int kk = 0; kk < 8; kk++)
            f[kk] = vW2[((size_t)v * 64 + j * 8 + kk) * 64 + n];
        store8h(g_w2Bh, ((size_t)v * 64 + n) * 64 + j * 8, f);
    } else if (id < 81920) {             // vWg: [v][128 n][64 k]
        id -= 49152;
        int j = id & 7, n = (id >> 3) & 127, v = id >> 10;
        #pragma unroll
        for (int kk = 0; kk < 8; kk++)
            f[kk] = vWg[((size_t)v * 64 + j * 8 + kk) * 128 + n];
        store8h(g_wgB2h, ((size_t)v * 128 + n) * 64 + j * 8, f);
    }
}

// ============================================================
// kA1m: Y[N,64] = flat[N,2048] @ [W1|Ws] (+bias) via mma.sync (3-term)
// ============================================================
#define A1_XHI 0
#define A1_XLO 18432
#define A1_BH  36864
#define A1_BL  46080
#define A1_SMEM 55296

__global__ void __launch_bounds__(256, 2) kA1m(
    const float* __restrict__ x, const float* __restrict__ b1,
    const float* __restrict__ bs) {
    extern __shared__ __align__(16) char sm[];
    const int tid = threadIdx.x, lane = tid & 31;
    const int warp = tid >> 5, g = lane >> 2, tg = lane & 3;
    const int r0 = warp * 16, tok0 = blockIdx.x * 128;

    float acc[8][4];
    #pragma unroll
    for (int nt = 0; nt < 8; nt++)
        acc[nt][0] = acc[nt][1] = acc[nt][2] = acc[nt][3] = 0.f;

    for (int kc = 0; kc < 32; kc++) {
        stage_x_split(sm, A1_XHI, A1_XLO, x, tok0, kc * 64, tid);
        stage_w64(sm, A1_BH, g_wgBh + kc * 64, 2048, tid);
        stage_w64(sm, A1_BL, g_wgBl + kc * 64, 2048, tid);
        __syncthreads();
        gemm3<8>(sm, A1_XHI, A1_XLO, A1_BH, A1_BL, r0, g, tg, acc);
        __syncthreads();
    }

    #pragma unroll
    for (int nt = 0; nt < 8; nt++) {
        int c = nt * 8 + tg * 2;
        float bb0 = (c < 32) ? b1[c] : bs[c - 32];
        float bb1 = (c + 1 < 32) ? b1[c + 1] : bs[c + 1 - 32];
        float* yA = &g_y[(size_t)(tok0 + r0 + g) * 64 + c];
        float* yB = &g_y[(size_t)(tok0 + r0 + g + 8) * 64 + c];
        yA[0] = acc[nt][0] + bb0; yA[1] = acc[nt][1] + bb1;
        yB[0] = acc[nt][2] + bb0; yB[1] = acc[nt][3] + bb1;
    }
}

// ============================================================
// kA2: per-token tail of the weight GRN (fp32, cheap)
// ============================================================
__global__ void __launch_bounds__(256) kA2(
    const float* __restrict__ W2, const float* __restrict__ b2,
    const float* __restrict__ Wg, const float* __restrict__ bg,
    const float* __restrict__ gam, const float* __restrict__ bet, int N) {
    __shared__ float W2s[32 * 33];
    __shared__ float Wgs[32 * 64];
    const int tid = threadIdx.x;
    for (int i = tid; i < 1024; i += 256) W2s[(i >> 5) * 33 + (i & 31)] = W2[i];
    for (int i = tid; i < 2048; i += 256) Wgs[i] = Wg[i];
    __syncthreads();

    const int lane = tid & 31, warp = tid >> 5;
    const int tok = blockIdx.x * 8 + warp;
    if (tok >= N) return;

    const float* y = &g_y[(size_t)tok * 64];
    float h = eluf_(y[lane]);
    float skip = y[32 + lane];

    float t = b2[lane];
    #pragma unroll
    for (int i = 0; i < 32; i++)
        t = fmaf(__shfl_sync(0xffffffffu, h, i), W2s[i * 33 + lane], t);

    float ga = bg[lane], gb = bg[32 + lane];
    #pragma unroll
    for (int i = 0; i < 32; i++) {
        float tv = __shfl_sync(0xffffffffu, t, i);
        ga = fmaf(tv, Wgs[i * 64 + lane], ga);
        gb = fmaf(tv, Wgs[i * 64 + 32 + lane], gb);
    }

    float z = skip + ga * sigmoidf_(gb);
    float m = wsum_(z) * (1.f / 32.f);
    float d = z - m;
    float var = wsum_(d * d) * (1.f / 32.f);
    float zn = d * rsqrtf(var + 1e-5f) * gam[lane] + bet[lane];

    float mx = wmax_(zn);
    float e = __expf(zn - mx);
    float se = wsum_(e);
    g_w[(size_t)tok * VD + lane] = e / se;
}

// ============================================================
// kBm: per-variable GRNs + weighted combine (single-term bf16 GEMMs,
//      exact fp32 skip via hi+lo x tiles). 94KB smem -> 2 CTAs/SM.
// ============================================================
#define KB_XHI  0
#define KB_XLO  18432
#define KB_W1   36864
#define KB_W2   46080
#define KB_WG   55296
#define KB_H    73728
#define KB_BIAS 92160
#define KB_SMEM (92160 + 2048)

__global__ void __launch_bounds__(256, 2) kBm(
    const float* __restrict__ x,
    const float* __restrict__ vb1, const float* __restrict__ vb2,
    const float* __restrict__ vbg, const float* __restrict__ vgam,
    const float* __restrict__ vbet, float* __restrict__ out) {
    extern __shared__ __align__(16) char sm[];
    float* b1s  = (float*)(sm + KB_BIAS);        // 64
    float* b2s  = b1s + 64;                      // 64
    float* bgs  = b2s + 64;                      // 128
    float* gams = bgs + 128;                     // 64
    float* bets = gams + 64;                     // 64
    float* wvS  = bets + 64;                     // 128

    const int tid = threadIdx.x, lane = tid & 31;
    const int warp = tid >> 5, g = lane >> 2, tg = lane & 3;
    const int r0 = warp * 16, tok0 = blockIdx.x * 128;

    float oacc[2][16];
    #pragma unroll
    for (int s = 0; s < 2; s++)
        #pragma unroll
        for (int i = 0; i < 16; i++) oacc[s][i] = 0.f;

    for (int v = 0; v < VD; v++) {
        // ---- stage ----
        stage_x_split(sm, KB_XHI, KB_XLO, x, tok0, v * 64, tid);
        stage_w64(sm, KB_W1, g_w1Bh + (size_t)v * 4096, 64, tid);
        stage_w64(sm, KB_W2, g_w2Bh + (size_t)v * 4096, 64, tid);
        stage_w128(sm, KB_WG, g_wgB2h + (size_t)v * 8192, tid);
        if (tid < 64) {
            b1s[tid]  = vb1[(size_t)v * 64 + tid];
            b2s[tid]  = vb2[(size_t)v * 64 + tid];
            gams[tid] = vgam[(size_t)v * 64 + tid];
            bets[tid] = vbet[(size_t)v * 64 + tid];
        } else if (tid < 192) {
            bgs[tid - 64] = vbg[(size_t)v * 128 + (tid - 64)];
        }
        if (tid < 128) wvS[tid] = g_w[(size_t)(tok0 + tid) * VD + v];
        __syncthreads();

        // ---- GEMM1: H = elu(Xh @ W1 + b1) ----
        {
            float acc[8][4];
            #pragma unroll
            for (int nt = 0; nt < 8; nt++)
                acc[nt][0] = acc[nt][1] = acc[nt][2] = acc[nt][3] = 0.f;
            gemm1t<8>(sm, KB_XHI, KB_W1, r0, g, tg, acc);
            store_bf(sm, KB_H, r0, g, tg, acc, b1s, true);
        }
        __syncthreads();

        // ---- GEMM2: H2 = H @ W2 + b2 (then overwrite H buffer) ----
        {
            float acc[8][4];
            #pragma unroll
            for (int nt = 0; nt < 8; nt++)
                acc[nt][0] = acc[nt][1] = acc[nt][2] = acc[nt][3] = 0.f;
            gemm1t<8>(sm, KB_H, KB_W2, r0, g, tg, acc);
            __syncthreads();   // all warps done reading H1
            store_bf(sm, KB_H, r0, g, tg, acc, b2s, false);
        }
        __syncthreads();

        // ---- GEMM3: G = H2 @ Wg (N=128) + epilogue ----
        {
            float acc3[16][4];
            #pragma unroll
            for (int nt = 0; nt < 16; nt++)
                acc3[nt][0] = acc3[nt][1] = acc3[nt][2] = acc3[nt][3] = 0.f;
            gemm1t<16>(sm, KB_H, KB_WG, r0, g, tg, acc3);

            #pragma unroll
            for (int sel = 0; sel < 2; sel++) {
                const int row = r0 + g + sel * 8;
                const int di = sel * 2;
                float vals[16];
                float s1 = 0.f, s2 = 0.f;
                #pragma unroll
                for (int i = 0; i < 8; i++) {
                    int c = i * 8 + tg * 2;
                    u32 xh = *(const u32*)(sm + KB_XHI + (row * LDT + c) * 2);
                    u32 xl = *(const u32*)(sm + KB_XLO + (row * LDT + c) * 2);
                    float x0 = lo16f_(xh) + lo16f_(xl);
                    float x1 = hi16f_(xh) + hi16f_(xl);
                    float aL = acc3[i][di] + bgs[c];
                    float aR = acc3[i][di + 1] + bgs[c + 1];
                    float gL = acc3[8 + i][di] + bgs[64 + c];
                    float gR = acc3[8 + i][di + 1] + bgs[64 + c + 1];
                    float v0 = x0 + aL * sigmoidf_(gL);
                    float v1 = x1 + aR * sigmoidf_(gR);
                    vals[2 * i] = v0; vals[2 * i + 1] = v1;
                    s1 += v0 + v1;
                    s2 += v0 * v0 + v1 * v1;
                }
                s1 += __shfl_xor_sync(0xffffffffu, s1, 1);
                s1 += __shfl_xor_sync(0xffffffffu, s1, 2);
                s2 += __shfl_xor_sync(0xffffffffu, s2, 1);
                s2 += __shfl_xor_sync(0xffffffffu, s2, 2);
                float m = s1 * (1.f / 64.f);
                float var = fmaxf(s2 * (1.f / 64.f) - m * m, 0.f);
                float rs = rsqrtf(var + 1e-5f);
                float wv = wvS[row];
                #pragma unroll
                for (int i = 0; i < 8; i++) {
                    int c = i * 8 + tg * 2;
                    float pv0 = (vals[2 * i] - m) * rs * gams[c] + bets[c];
                    float pv1 = (vals[2 * i + 1] - m) * rs * gams[c + 1] + bets[c + 1];
                    oacc[sel][2 * i]     = fmaf(wv, pv0, oacc[sel][2 * i]);
                    oacc[sel][2 * i + 1] = fmaf(wv, pv1, oacc[sel][2 * i + 1]);
                }
            }
        }
        __syncthreads();   // done reading X/H before next stage overwrites
    }

    #pragma unroll
    for (int sel = 0; sel < 2; sel++) {
        int row = r0 + g + sel * 8;
        float* op = &out[(size_t)(tok0 + row) * 64];
        #pragma unroll
        for (int i = 0; i < 8; i++) {
            int c = i * 8 + tg * 2;
            *(float2*)&op[c] = make_float2(oacc[sel][2 * i], oacc[sel][2 * i + 1]);
        }
    }
}

// ============================================================
extern "C" void kernel_launch(void* const* d_in, const int* in_sizes, int n_in,
                              void* d_out, int out_size) {
    const float* x     = (const float*)d_in[0];
    const float* wgW1  = (const float*)d_in[1];
    const float* wgb1  = (const float*)d_in[2];
    const float* wgW2  = (const float*)d_in[3];
    const float* wgb2  = (const float*)d_in[4];
    const float* wgWg  = (const float*)d_in[5];
    const float* wgbg  = (const float*)d_in[6];
    const float* wgWs  = (const float*)d_in[7];
    const float* wgbs  = (const float*)d_in[8];
    const float* wggam = (const float*)d_in[9];
    const float* wgbet = (const float*)d_in[10];
    const float* vW1   = (const float*)d_in[11];
    const float* vb1   = (const float*)d_in[12];
    const float* vW2   = (const float*)d_in[13];
    const float* vb2   = (const float*)d_in[14];
    const float* vWg   = (const float*)d_in[15];
    const float* vbg   = (const float*)d_in[16];
    const float* vgam  = (const float*)d_in[17];
    const float* vbet  = (const float*)d_in[18];
    float* out = (float*)d_out;

    int N = in_sizes[0] / KF;  // 32768

    kPrepW<<<320, 256>>>(wgW1, wgWs, vW1, vW2, vWg);

    cudaFuncSetAttribute(kA1m, cudaFuncAttributeMaxDynamicSharedMemorySize, A1_SMEM);
    kA1m<<<N / 128, 256, A1_SMEM>>>(x, wgb1, wgbs);

    kA2<<<(N + 7) / 8, 256>>>(wgW2, wgb2, wgWg, wgbg, wggam, wgbet, N);

    cudaFuncSetAttribute(kBm, cudaFuncAttributeMaxDynamicSharedMemorySize, KB_SMEM);
    kBm<<<N / 128, 256, KB_SMEM>>>(x, vb1, vb2, vbg, vgam, vbet, out);
}